// round 17
// baseline (speedup 1.0000x reference)
#include <cuda_runtime.h>
#include <cuda_fp16.h>
#include <math.h>
#include <stdint.h>

#define LEN 2048
#define DIM 2048
#define NH 16
#define HD 128
#define SCALE 0.08838834764831845f   /* 1/sqrt(128) */
#define LOG2E 1.4426950408889634f
#define SOFT_OFF (4.0f * LOG2E)      /* fixed softmax offset, log2 domain */

// ---------------- scratch (allocation-free: __device__ globals) ----------------
__device__ __half g_qkv[(size_t)LEN * 3 * DIM];              // [L, 3*DIM] fp16

__device__ __half g_xh[(size_t)LEN * DIM];                   // x (fp16)
__device__ __half g_wqh[(size_t)3 * DIM * DIM];              // w_qkv (fp16)
__device__ __half g_wph[(size_t)DIM * DIM];                  // w_proj (fp16)
__device__ __half g_qh[(size_t)NH * LEN * HD];               // q*SCALE*log2e [H,L,D]
__device__ __half g_kh[(size_t)NH * LEN * HD];               // k (fp16) [H,L,D]
__device__ __half g_vth[(size_t)NH * HD * LEN];              // v^T (fp16) [H,D,L]
__device__ __half g_oh[(size_t)LEN * DIM];                   // O (fp16) [L, H*D]

// ---------------- helpers ----------------
static __device__ __forceinline__ unsigned cvta_smem(const void* p) {
    return (unsigned)__cvta_generic_to_shared(p);
}
static __device__ __forceinline__ unsigned pack2h(float x0, float x1) {
    __half2 h = __floats2half2_rn(x0, x1);
    return *reinterpret_cast<unsigned*>(&h);
}

#define LDSM4(r0, r1, r2, r3, addr)                                         \
    asm volatile("ldmatrix.sync.aligned.m8n8.x4.shared.b16 {%0,%1,%2,%3}, [%4];" \
                 : "=r"(r0), "=r"(r1), "=r"(r2), "=r"(r3) : "r"(addr))

#define MMA16816(d, a, b0_, b1_)                                            \
    asm volatile("mma.sync.aligned.m16n8k16.row.col.f32.f16.f16.f32 "      \
                 "{%0,%1,%2,%3},{%4,%5,%6,%7},{%8,%9},{%0,%1,%2,%3};"      \
                 : "+f"(d[0]), "+f"(d[1]), "+f"(d[2]), "+f"(d[3])           \
                 : "r"(a[0]), "r"(a[1]), "r"(a[2]), "r"(a[3]),              \
                   "r"(b0_), "r"(b1_))

#define CP_ASYNC16(dst, src) \
    asm volatile("cp.async.cg.shared.global [%0], [%1], 16;" \
                 :: "r"(dst), "l"(src) : "memory")
#define CP_COMMIT() asm volatile("cp.async.commit_group;" ::: "memory")
#define CP_WAIT1()  asm volatile("cp.async.wait_group 1;" ::: "memory")
#define CP_WAIT0()  asm volatile("cp.async.wait_group 0;" ::: "memory")

// ================= generic fp16 NT GEMM (128x128 tile, 2 CTAs/SM) =============
template<int ROWS>
static __device__ __forceinline__ void load_tile(
    unsigned sbase, const __half* __restrict__ A,
    int ld, int kbase, int tid)
{
#pragma unroll
    for (int i = 0; i < ROWS / 32; ++i) {
        const int idx = tid + i * 256;
        const int row = idx >> 3;
        const int ch  = idx & 7;
        const unsigned dst = sbase + row * 128 + ((ch * 16) ^ ((row & 7) * 16));
        const __half* src = A + (long long)row * ld + kbase + ch * 8;
        CP_ASYNC16(dst, src);
    }
}

template<typename OUT>
__global__ __launch_bounds__(256, 2)
void gemm_nt_h2(const __half* __restrict__ Ah,
                const __half* __restrict__ Bh,
                OUT* __restrict__ C,
                int K, int lda, int ldb, int ldc,
                float alpha, const float* __restrict__ bias)
{
    constexpr int NT16  = 2;           // WN=32
    constexpr int AT    = 128 * 64 * 2;
    constexpr int BT    = 128 * 64 * 2;
    constexpr int STAGE = AT + BT;     // 32768

    extern __shared__ char smem[];
    const unsigned smem_b = cvta_smem(smem);

    const int tid  = threadIdx.x;
    const int wid  = tid >> 5;
    const int lane = tid & 31;
    const int wm = (wid >> 2) * 64;
    const int wn = (wid & 3) * 32;
    const int m0 = blockIdx.y * 128;
    const int n0 = blockIdx.x * 128;

    const __half* pAh = Ah + (long long)m0 * lda;
    const __half* pBh = Bh + (long long)n0 * ldb;

    unsigned offA0[4], mskA[4];
    const unsigned cbA = ((lane >> 4) & 1) * 16;
#pragma unroll
    for (int mt = 0; mt < 4; ++mt) {
        const int r = wm + mt * 16 + (lane & 15);
        offA0[mt] = r * 128;
        mskA[mt]  = (r & 7) * 16;
    }
    unsigned offB0[NT16], mskB[NT16];
    const unsigned cbB = ((lane >> 3) & 1) * 16;
#pragma unroll
    for (int p = 0; p < NT16; ++p) {
        const int r = wn + p * 16 + (lane & 7) + ((lane >> 4) & 1) * 8;
        offB0[p] = r * 128;
        mskB[p]  = (r & 7) * 16;
    }

    float acc[4][2 * NT16][4];
#pragma unroll
    for (int i = 0; i < 4; ++i)
#pragma unroll
        for (int j = 0; j < 2 * NT16; ++j)
#pragma unroll
            for (int v = 0; v < 4; ++v) acc[i][j][v] = 0.0f;

    const int nch = K >> 6;

#pragma unroll
    for (int pc = 0; pc < 2; ++pc) {
        const unsigned sb = smem_b + pc * STAGE;
        const int kb = pc * 64;
        load_tile<128>(sb, pAh, lda, kb, tid);
        load_tile<128>(sb + AT, pBh, ldb, kb, tid);
        CP_COMMIT();
    }

    for (int c = 0; c < nch; ++c) {
        if (c + 1 < nch) { CP_WAIT1(); } else { CP_WAIT0(); }
        __syncthreads();

        if (c + 2 < nch) {
            const unsigned sb2 = smem_b + ((c + 2) % 3) * STAGE;
            const int kb = (c + 2) * 64;
            load_tile<128>(sb2, pAh, lda, kb, tid);
            load_tile<128>(sb2 + AT, pBh, ldb, kb, tid);
            CP_COMMIT();
        }

        const unsigned sb = smem_b + (c % 3) * STAGE;
#pragma unroll
        for (int ks = 0; ks < 4; ++ks) {
            const unsigned kb = ks * 32;
            unsigned ah[4][4];
#pragma unroll
            for (int mt = 0; mt < 4; ++mt) {
                const unsigned a0 = sb + offA0[mt] + ((cbA + kb) ^ mskA[mt]);
                LDSM4(ah[mt][0], ah[mt][1], ah[mt][2], ah[mt][3], a0);
            }
#pragma unroll
            for (int p = 0; p < NT16; ++p) {
                const unsigned b0 = sb + AT + offB0[p] + ((cbB + kb) ^ mskB[p]);
                unsigned bh[4];
                LDSM4(bh[0], bh[1], bh[2], bh[3], b0);
#pragma unroll
                for (int mt = 0; mt < 4; ++mt) {
                    MMA16816(acc[mt][2 * p],     ah[mt], bh[0], bh[1]);
                    MMA16816(acc[mt][2 * p + 1], ah[mt], bh[2], bh[3]);
                }
            }
        }
    }

    const int g  = lane >> 2;
    const int tg = lane & 3;
#pragma unroll
    for (int mt = 0; mt < 4; ++mt) {
#pragma unroll
        for (int nt = 0; nt < 2 * NT16; ++nt) {
            const int r = m0 + wm + mt * 16 + g;
            const int c = n0 + wn + nt * 8 + tg * 2;
            float bx = 0.0f, by = 0.0f;
            if (bias) { bx = bias[c]; by = bias[c + 1]; }
            const float v00 = acc[mt][nt][0] * alpha + bx;
            const float v01 = acc[mt][nt][1] * alpha + by;
            const float v10 = acc[mt][nt][2] * alpha + bx;
            const float v11 = acc[mt][nt][3] * alpha + by;
            if (sizeof(OUT) == 4) {
                *reinterpret_cast<float2*>((float*)C + (long long)r * ldc + c) =
                    make_float2(v00, v01);
                *reinterpret_cast<float2*>((float*)C + (long long)(r + 8) * ldc + c) =
                    make_float2(v10, v11);
            } else {
                *reinterpret_cast<unsigned*>((__half*)C + (long long)r * ldc + c) =
                    pack2h(v00, v01);
                *reinterpret_cast<unsigned*>((__half*)C + (long long)(r + 8) * ldc + c) =
                    pack2h(v10, v11);
            }
        }
    }
}

#define GSMEM (3 * 32768)   /* 98304: 2 CTAs/SM */

// ================= flash attention (2 CTAs/SM, 64-key blocks) =================
// grid (16 q-blocks, 16 heads), 256 threads (8 warps), each warp owns 16 q rows.
// smem: Q 32K (128x128, 256B pitch) | K 2x16K (64x128, 256B pitch)
//       | V 2x16K (128x64, 128B pitch) = 96KB -> 2 CTAs/SM.
// No-max softmax (QKNorm bound), fp32 exp2, 2-stage K/V pipeline.
#define FA_SMEM (96 * 1024)

// 128 rows x 128 cols fp16, 256B pitch (Q)
static __device__ __forceinline__ void fa_load_q(
    unsigned dst, const __half* __restrict__ src, int tid)
{
#pragma unroll
    for (int i = 0; i < 8; ++i) {
        const int idx = tid + i * 256;
        const int row = idx >> 4;
        const int ch  = idx & 15;
        const unsigned d = dst + row * 256 + ((ch * 16) ^ ((row & 7) * 16));
        CP_ASYNC16(d, src + (long long)row * HD + ch * 8);
    }
}
// 64 rows x 128 cols fp16, 256B pitch (K block)
static __device__ __forceinline__ void fa_load_k(
    unsigned dst, const __half* __restrict__ src, int tid)
{
#pragma unroll
    for (int i = 0; i < 4; ++i) {
        const int idx = tid + i * 256;
        const int row = idx >> 4;
        const int ch  = idx & 15;
        const unsigned d = dst + row * 256 + ((ch * 16) ^ ((row & 7) * 16));
        CP_ASYNC16(d, src + (long long)row * HD + ch * 8);
    }
}
// 128 rows x 64 cols fp16, 128B pitch (V block; rows = head dim, ld = LEN)
static __device__ __forceinline__ void fa_load_v(
    unsigned dst, const __half* __restrict__ src, int tid)
{
#pragma unroll
    for (int i = 0; i < 4; ++i) {
        const int idx = tid + i * 256;
        const int row = idx >> 3;
        const int ch  = idx & 7;
        const unsigned d = dst + row * 128 + ((ch * 16) ^ ((row & 7) * 16));
        CP_ASYNC16(d, src + (long long)row * LEN + ch * 8);
    }
}

__global__ __launch_bounds__(256, 2)
void flash_attn()
{
    extern __shared__ char smem[];
    const unsigned sb  = cvta_smem(smem);
    const unsigned sQ  = sb;
    const unsigned sK  = sb + 32768;     // + (j&1)*16384
    const unsigned sV  = sb + 65536;     // + (j&1)*16384

    const int tid  = threadIdx.x;
    const int wid  = tid >> 5;
    const int lane = tid & 31;
    const int qb = blockIdx.x;
    const int h  = blockIdx.y;

    const __half* Qh = g_qh + ((size_t)h * LEN + qb * 128) * HD;
    const __half* Kh = g_kh + (size_t)h * LEN * HD;
    const __half* Vt = g_vth + (size_t)h * HD * LEN;

    // prologue: {Q, K0, V0}, {K1, V1}
    fa_load_q(sQ, Qh, tid);
    fa_load_k(sK, Kh, tid);
    fa_load_v(sV, Vt, tid);
    CP_COMMIT();
    fa_load_k(sK + 16384, Kh + 64 * HD, tid);
    fa_load_v(sV + 16384, Vt + 64, tid);
    CP_COMMIT();

    const int q0 = wid * 16;
    const unsigned rowA256 = (q0 + (lane & 15)) * 256;
    const unsigned mskA    = (lane & 7) * 16;
    const unsigned caA     = ((lane >> 4) & 1) * 16;
    const int rB0          = (lane & 7) + ((lane >> 4) & 1) * 8;
    const unsigned rowBK   = rB0 * 256;   // K tile pitch 256B
    const unsigned rowBV   = rB0 * 128;   // V tile pitch 128B
    const unsigned mskB    = (rB0 & 7) * 16;
    const unsigned cbB     = ((lane >> 3) & 1) * 16;

    float o[16][4];
#pragma unroll
    for (int i = 0; i < 16; ++i)
#pragma unroll
        for (int v = 0; v < 4; ++v) o[i][v] = 0.0f;
    float l0 = 0.0f, l1 = 0.0f;

    const int NB = LEN / 64;   // 32 key blocks
    for (int j = 0; j < NB; ++j) {
        if (j + 1 < NB) { CP_WAIT1(); } else { CP_WAIT0(); }
        __syncthreads();

        const unsigned kbuf = sK + (j & 1) * 16384;
        const unsigned vbuf = sV + (j & 1) * 16384;

        // ---- S = Q @ K^T + (-offset), log2 domain (64 keys) ----
        float s[8][4];
#pragma unroll
        for (int i = 0; i < 8; ++i)
#pragma unroll
            for (int v = 0; v < 4; ++v) s[i][v] = -SOFT_OFF;

#pragma unroll
        for (int kd = 0; kd < 8; ++kd) {
            unsigned aq[4];
            LDSM4(aq[0], aq[1], aq[2], aq[3],
                  sQ + rowA256 + ((kd * 32 + caA) ^ mskA));
            const unsigned cb = (kd * 32 + cbB) ^ mskB;
#pragma unroll
            for (int p = 0; p < 4; ++p) {
                unsigned bk[4];
                LDSM4(bk[0], bk[1], bk[2], bk[3], kbuf + rowBK + p * 4096 + cb);
                MMA16816(s[2 * p],     aq, bk[0], bk[1]);
                MMA16816(s[2 * p + 1], aq, bk[2], bk[3]);
            }
        }

        // ---- fp32 exp2 + row-sum + PV per key-16 tile ----
#pragma unroll
        for (int kt = 0; kt < 4; ++kt) {
            const float e00 = exp2f(s[2 * kt][0]);
            const float e01 = exp2f(s[2 * kt][1]);
            const float e02 = exp2f(s[2 * kt][2]);
            const float e03 = exp2f(s[2 * kt][3]);
            const float e10 = exp2f(s[2 * kt + 1][0]);
            const float e11 = exp2f(s[2 * kt + 1][1]);
            const float e12 = exp2f(s[2 * kt + 1][2]);
            const float e13 = exp2f(s[2 * kt + 1][3]);
            l0 += e00; l0 += e01; l1 += e02; l1 += e03;
            l0 += e10; l0 += e11; l1 += e12; l1 += e13;
            unsigned ph[4];
            ph[0] = pack2h(e00, e01);
            ph[1] = pack2h(e02, e03);
            ph[2] = pack2h(e10, e11);
            ph[3] = pack2h(e12, e13);

            const unsigned cb = (kt * 32 + cbB) ^ mskB;
#pragma unroll
            for (int dt = 0; dt < 8; ++dt) {
                unsigned bv[4];
                LDSM4(bv[0], bv[1], bv[2], bv[3], vbuf + rowBV + dt * 2048 + cb);
                MMA16816(o[2 * dt],     ph, bv[0], bv[1]);
                MMA16816(o[2 * dt + 1], ph, bv[2], bv[3]);
            }
        }

        __syncthreads();
        if (j + 2 < NB) {
            fa_load_k(sK + (j & 1) * 16384, Kh + (long long)(j + 2) * 64 * HD, tid);
            fa_load_v(sV + (j & 1) * 16384, Vt + (j + 2) * 64, tid);
            CP_COMMIT();
        }
    }

    // ---- epilogue: normalize, store fp16 O [L, H*D] ----
    l0 += __shfl_xor_sync(0xffffffffu, l0, 1);
    l0 += __shfl_xor_sync(0xffffffffu, l0, 2);
    l1 += __shfl_xor_sync(0xffffffffu, l1, 1);
    l1 += __shfl_xor_sync(0xffffffffu, l1, 2);
    const float inv0 = 1.0f / l0;
    const float inv1 = 1.0f / l1;

    const int r0g = qb * 128 + q0 + (lane >> 2);
#pragma unroll
    for (int nt = 0; nt < 16; ++nt) {
        const int d = nt * 8 + (lane & 3) * 2;
        const size_t i0 = (size_t)r0g * DIM + h * HD + d;
        const size_t i1 = i0 + (size_t)8 * DIM;
        *reinterpret_cast<unsigned*>(&g_oh[i0]) =
            pack2h(o[nt][0] * inv0, o[nt][1] * inv0);
        *reinterpret_cast<unsigned*>(&g_oh[i1]) =
            pack2h(o[nt][2] * inv1, o[nt][3] * inv1);
    }
}

// ---------------- round x / w_qkv / w_proj to fp16 ----------------
#define SEG_X  (LEN * DIM / 4)
#define SEG_WQ (3 * DIM * DIM / 4)
#define SEG_WP (DIM * DIM / 4)
__global__ void split_inputs(const float* __restrict__ x,
                             const float* __restrict__ wq,
                             const float* __restrict__ wp)
{
    const int i = blockIdx.x * blockDim.x + threadIdx.x;
    if (i < SEG_X) {
        float4 v = reinterpret_cast<const float4*>(x)[i];
        reinterpret_cast<uint2*>(g_xh)[i] =
            make_uint2(pack2h(v.x, v.y), pack2h(v.z, v.w));
    } else if (i < SEG_X + SEG_WQ) {
        const int j = i - SEG_X;
        float4 v = reinterpret_cast<const float4*>(wq)[j];
        reinterpret_cast<uint2*>(g_wqh)[j] =
            make_uint2(pack2h(v.x, v.y), pack2h(v.z, v.w));
    } else if (i < SEG_X + SEG_WQ + SEG_WP) {
        const int j = i - SEG_X - SEG_WQ;
        float4 v = reinterpret_cast<const float4*>(wp)[j];
        reinterpret_cast<uint2*>(g_wph)[j] =
            make_uint2(pack2h(v.x, v.y), pack2h(v.z, v.w));
    }
}

// ---------------- QK RMSNorm + RoPE + V transpose ----------------
// grid 2048 (l), block 512: warp w = head w; lane owns dims 4*lane..4*lane+3.
__global__ __launch_bounds__(512, 2)
void qknorm_rope(const float* __restrict__ pe,
                 const float* __restrict__ qs,
                 const float* __restrict__ ks)
{
    const int l = blockIdx.x;
    const int h = threadIdx.x >> 5;
    const int lane = threadIdx.x & 31;
    const int d0 = lane * 4;

    const __half* base = g_qkv + (size_t)l * (3 * DIM) + h * HD + d0;
    __half2 qv[2], kv[2], vv[2];
    *reinterpret_cast<uint2*>(qv) = *reinterpret_cast<const uint2*>(base);
    *reinterpret_cast<uint2*>(kv) = *reinterpret_cast<const uint2*>(base + DIM);
    *reinterpret_cast<uint2*>(vv) = *reinterpret_cast<const uint2*>(base + 2 * DIM);

    float q[4], k[4];
    {
        float2 t;
        t = __half22float2(qv[0]); q[0] = t.x; q[1] = t.y;
        t = __half22float2(qv[1]); q[2] = t.x; q[3] = t.y;
        t = __half22float2(kv[0]); k[0] = t.x; k[1] = t.y;
        t = __half22float2(kv[1]); k[2] = t.x; k[3] = t.y;
    }

    float sq = q[0] * q[0] + q[1] * q[1] + q[2] * q[2] + q[3] * q[3];
    float sk = k[0] * k[0] + k[1] * k[1] + k[2] * k[2] + k[3] * k[3];
#pragma unroll
    for (int o = 16; o; o >>= 1) {
        sq += __shfl_xor_sync(0xffffffffu, sq, o);
        sk += __shfl_xor_sync(0xffffffffu, sk, o);
    }
    const float rrq = rsqrtf(sq * (1.0f / HD) + 1e-6f);
    const float rrk = rsqrtf(sk * (1.0f / HD) + 1e-6f);

    float4 qsv = *reinterpret_cast<const float4*>(&qs[d0]);
    float4 ksv = *reinterpret_cast<const float4*>(&ks[d0]);
    float qn[4], kn[4];
    qn[0] = q[0] * rrq * qsv.x; qn[1] = q[1] * rrq * qsv.y;
    qn[2] = q[2] * rrq * qsv.z; qn[3] = q[3] * rrq * qsv.w;
    kn[0] = k[0] * rrk * ksv.x; kn[1] = k[1] * rrk * ksv.y;
    kn[2] = k[2] * rrk * ksv.z; kn[3] = k[3] * rrk * ksv.w;

    const float* pp = pe + (size_t)l * 256 + d0 * 2;
    float4 p0 = *reinterpret_cast<const float4*>(pp);
    float4 p1 = *reinterpret_cast<const float4*>(pp + 4);
    const float cs = SCALE * LOG2E;
    float qr[4], kr[4];
    qr[0] = (p0.x * qn[0] + p0.y * qn[1]) * cs;
    qr[1] = (p0.z * qn[0] + p0.w * qn[1]) * cs;
    qr[2] = (p1.x * qn[2] + p1.y * qn[3]) * cs;
    qr[3] = (p1.z * qn[2] + p1.w * qn[3]) * cs;
    kr[0] = p0.x * kn[0] + p0.y * kn[1];
    kr[1] = p0.z * kn[0] + p0.w * kn[1];
    kr[2] = p1.x * kn[2] + p1.y * kn[3];
    kr[3] = p1.z * kn[2] + p1.w * kn[3];

    const size_t idx = ((size_t)h * LEN + l) * HD + d0;
    *reinterpret_cast<uint2*>(&g_qh[idx]) =
        make_uint2(pack2h(qr[0], qr[1]), pack2h(qr[2], qr[3]));
    *reinterpret_cast<uint2*>(&g_kh[idx]) =
        make_uint2(pack2h(kr[0], kr[1]), pack2h(kr[2], kr[3]));

    const size_t vb = (size_t)h * HD * LEN + l;
    g_vth[vb + (size_t)(d0 + 0) * LEN] = vv[0].x;
    g_vth[vb + (size_t)(d0 + 1) * LEN] = vv[0].y;
    g_vth[vb + (size_t)(d0 + 2) * LEN] = vv[1].x;
    g_vth[vb + (size_t)(d0 + 3) * LEN] = vv[1].y;
}

// ---------------- launch ----------------
extern "C" void kernel_launch(void* const* d_in, const int* in_sizes, int n_in,
                              void* d_out, int out_size)
{
    const float* x      = (const float*)d_in[0];
    const float* pe     = (const float*)d_in[1];
    const float* w_qkv  = (const float*)d_in[2];
    const float* q_sc   = (const float*)d_in[3];
    const float* k_sc   = (const float*)d_in[4];
    const float* w_proj = (const float*)d_in[5];
    const float* b_proj = (const float*)d_in[6];
    float* out = (float*)d_out;

    __half *p_qkv, *p_xh, *p_wqh, *p_wph, *p_oh;
    cudaGetSymbolAddress((void**)&p_qkv, g_qkv);
    cudaGetSymbolAddress((void**)&p_xh,  g_xh);
    cudaGetSymbolAddress((void**)&p_wqh, g_wqh);
    cudaGetSymbolAddress((void**)&p_wph, g_wph);
    cudaGetSymbolAddress((void**)&p_oh,  g_oh);

    cudaFuncSetAttribute((const void*)gemm_nt_h2<__half>,
                         cudaFuncAttributeMaxDynamicSharedMemorySize, GSMEM);
    cudaFuncSetAttribute((const void*)gemm_nt_h2<float>,
                         cudaFuncAttributeMaxDynamicSharedMemorySize, GSMEM);
    cudaFuncSetAttribute((const void*)flash_attn,
                         cudaFuncAttributeMaxDynamicSharedMemorySize, FA_SMEM);

    // 0) round x, weights to fp16
    {
        const int total = SEG_X + SEG_WQ + SEG_WP;
        split_inputs<<<(total + 255) / 256, 256>>>(x, w_qkv, w_proj);
    }

    // 1) QKV = x @ w_qkv^T : [2048, 6144] fp16 output
    gemm_nt_h2<__half><<<dim3(6144 / 128, 2048 / 128, 1), 256, GSMEM>>>(
        p_xh, p_wqh, p_qkv, 2048, 2048, 2048, 6144, 1.0f, nullptr);

    // 2) QK RMSNorm + RoPE + V transpose (SCALE*log2e folded into Q)
    qknorm_rope<<<LEN, 512>>>(pe, q_sc, k_sc);

    // 3) fused attention (fp32 exp2, 64-key blocks, 2 CTAs/SM)
    flash_attn<<<dim3(LEN / 128, NH), 256, FA_SMEM>>>();

    // 4) out = O @ w_proj^T + b_proj : [2048, 2048] fp32
    gemm_nt_h2<float><<<dim3(2048 / 128, 2048 / 128, 1), 256, GSMEM>>>(
        p_oh, p_wph, out, 2048, 2048, 2048, 2048, 1.0f, b_proj);
}